// round 2
// baseline (speedup 1.0000x reference)
#include <cuda_runtime.h>
#include <math.h>

#define Mdim 2048
#define Ndim 256
#define Kdim 256
#define ITERS 1000
#define JS 216            // rows of Minv kept in shared memory (216 KB)
#define JTAIL (Ndim - JS) // 40 rows held in registers per thread

// Scratch (allocation-free rule: __device__ globals)
__device__ float g_G[Ndim * Ndim];     // G = A^T A + rho I, inverted in place -> Minv
__device__ float g_Atb[Ndim * Kdim];   // A^T b

// ---------------------------------------------------------------------------
// C = A^T X  (A: [M,N], X: [M,K], C: [N,K]), optionally += rho*I on diagonal
// ---------------------------------------------------------------------------
__global__ void atx_kernel(const float* __restrict__ A, const float* __restrict__ X,
                           float* __restrict__ C, const float* __restrict__ rho_p,
                           int addDiag)
{
    __shared__ float As[32][33];
    __shared__ float Xs[32][33];
    const int tx = threadIdx.x, ty = threadIdx.y;
    const int i0 = blockIdx.x * 32, j0 = blockIdx.y * 32;
    float acc = 0.f;
    for (int mt = 0; mt < Mdim; mt += 32) {
        As[ty][tx] = A[(mt + ty) * Ndim + i0 + tx];
        Xs[ty][tx] = X[(mt + ty) * Kdim + j0 + tx];
        __syncthreads();
#pragma unroll
        for (int mm = 0; mm < 32; mm++)
            acc = fmaf(As[mm][ty], Xs[mm][tx], acc);
        __syncthreads();
    }
    const int i = i0 + ty, j = j0 + tx;
    if (addDiag && i == j) acc += fabsf(rho_p[0]) + 1e-10f;
    C[i * Kdim + j] = acc;
}

// ---------------------------------------------------------------------------
// In-place Gauss-Jordan inverse of SPD 256x256 (no pivoting needed for SPD).
// Single block, 1024 threads. Matrix in global scratch.
// ---------------------------------------------------------------------------
__global__ void gj_invert_kernel(float* __restrict__ Ag)
{
    __shared__ float rowk[Ndim];
    __shared__ float colk[Ndim];
    __shared__ float pinv_s;
    const int tid = threadIdx.x;  // 1024 threads

    for (int k = 0; k < Ndim; k++) {
        if (tid == 0) pinv_s = 1.0f / Ag[k * Ndim + k];
        __syncthreads();
        const float pinv = pinv_s;
        if (tid < Ndim) {
            colk[tid] = Ag[tid * Ndim + k];            // snapshot column k
            rowk[tid] = Ag[k * Ndim + tid] * pinv;     // scaled pivot row
        }
        __syncthreads();
        for (int idx = tid; idx < Ndim * Ndim; idx += 1024) {
            const int i = idx >> 8;
            const int j = idx & 255;
            float v;
            if (i == k)      v = (j == k) ? pinv : rowk[j];
            else if (j == k) v = -colk[i] * pinv;
            else             v = Ag[idx] - colk[i] * rowk[j];
            Ag[idx] = v;
        }
        __syncthreads();
    }
}

// ---------------------------------------------------------------------------
// Persistent ADMM: 64 blocks x 4 columns each, 256 threads (thread = row).
// Minv rows [0,JS) in SMEM (loaded once); rows [JS,256) of this thread's
// Minv column preloaded into registers (iteration-invariant). z, u, Atb in
// registers. Double-buffered w_s -> one barrier per iteration.
// Uses Minv symmetry: Tpred[t] = sum_j Minv[j][t] * w[j].
// ---------------------------------------------------------------------------
__global__ void __launch_bounds__(256, 1) admm_kernel(
    const float* __restrict__ Minv, const float* __restrict__ Atb,
    const float* __restrict__ rho_p, const float* __restrict__ lam_p,
    float* __restrict__ out)
{
    extern __shared__ float sm[];
    float* MinvS = sm;                    // JS * 256 floats
    float* wbuf0 = sm + JS * Ndim;        // 256 * 4 floats
    float* wbuf1 = wbuf0 + Ndim * 4;      // 256 * 4 floats

    const int t  = threadIdx.x;
    const int c0 = blockIdx.x * 4;

    const float rho = fabsf(rho_p[0]) + 1e-10f;
    const float tau = fabsf(lam_p[0]) / rho;

    // Stage Minv rows [0, JS) into shared memory (coalesced float4)
    {
        const float4* src = (const float4*)Minv;
        float4* dst = (float4*)MinvS;
        for (int idx = t; idx < JS * Ndim / 4; idx += 256) dst[idx] = src[idx];
    }

    // Preload iteration-invariant tail of this thread's Minv column
    float mtail[JTAIL];
#pragma unroll
    for (int j = 0; j < JTAIL; j++)
        mtail[j] = __ldg(Minv + (JS + j) * Ndim + t);

    float atbr[4], z[4], u[4], tp[4];
#pragma unroll
    for (int c = 0; c < 4; c++) {
        atbr[c] = Atb[t * Kdim + c0 + c];
        z[c] = 0.f; u[c] = 0.f; tp[c] = 0.f;
    }
    __syncthreads();

    for (int it = 0; it < ITERS; ++it) {
        float* w_s = (it & 1) ? wbuf1 : wbuf0;

        // w[t][c] = Atb[t][c] + rho*(z-u)   (thread owns row t's state)
        float4 wv;
        wv.x = fmaf(rho, z[0] - u[0], atbr[0]);
        wv.y = fmaf(rho, z[1] - u[1], atbr[1]);
        wv.z = fmaf(rho, z[2] - u[2], atbr[2]);
        wv.w = fmaf(rho, z[3] - u[3], atbr[3]);
        *(float4*)&w_s[t * 4] = wv;
        __syncthreads();

        // matvec over 4 columns: acc[c] = sum_j Minv[j][t] * w[j][c]
        float a0 = 0.f, a1 = 0.f, a2 = 0.f, a3 = 0.f;
        const float* mp = MinvS + t;
#pragma unroll 8
        for (int j = 0; j < JS; j++) {
            const float m = mp[j * Ndim];
            const float4 w4 = *(const float4*)&w_s[j * 4];
            a0 = fmaf(m, w4.x, a0); a1 = fmaf(m, w4.y, a1);
            a2 = fmaf(m, w4.z, a2); a3 = fmaf(m, w4.w, a3);
        }
#pragma unroll 8
        for (int j = 0; j < JTAIL; j++) {
            const float m = mtail[j];
            const float4 w4 = *(const float4*)&w_s[(JS + j) * 4];
            a0 = fmaf(m, w4.x, a0); a1 = fmaf(m, w4.y, a1);
            a2 = fmaf(m, w4.z, a2); a3 = fmaf(m, w4.w, a3);
        }
        tp[0] = a0; tp[1] = a1; tp[2] = a2; tp[3] = a3;

        // soft-threshold + clip + dual update (elementwise, registers only)
#pragma unroll
        for (int c = 0; c < 4; c++) {
            const float g  = tp[c] + u[c];
            float zn = fmaxf(g - tau, 0.f) + fminf(g + tau, 0.f);
            zn = fminf(fmaxf(zn, 0.f), 1.f);
            u[c] = u[c] + tp[c] - zn;
            z[c] = zn;
        }
        // no trailing barrier: next iteration writes the OTHER w buffer;
        // its barrier orders those writes against this iteration's reads.
    }

#pragma unroll
    for (int c = 0; c < 4; c++) out[t * Kdim + c0 + c] = tp[c];
}

// ---------------------------------------------------------------------------
extern "C" void kernel_launch(void* const* d_in, const int* in_sizes, int n_in,
                              void* d_out, int out_size)
{
    // metadata order: T, s_A, s_mic_data, rho_param, lam_param
    const float* s_A   = (const float*)d_in[1];
    const float* s_mic = (const float*)d_in[2];
    const float* rho_p = (const float*)d_in[3];
    const float* lam_p = (const float*)d_in[4];
    float* out = (float*)d_out;

    float *G, *Atb;
    cudaGetSymbolAddress((void**)&G, g_G);
    cudaGetSymbolAddress((void**)&Atb, g_Atb);

    const size_t shmem = (size_t)(JS * Ndim + 2 * Ndim * 4) * sizeof(float);
    cudaFuncSetAttribute(admm_kernel, cudaFuncAttributeMaxDynamicSharedMemorySize,
                         (int)shmem);

    dim3 tb(32, 32);
    dim3 gb(8, 8);
    atx_kernel<<<gb, tb>>>(s_A, s_A,   G,   rho_p, 1);
    atx_kernel<<<gb, tb>>>(s_A, s_mic, Atb, rho_p, 0);
    gj_invert_kernel<<<1, 1024>>>(G);
    admm_kernel<<<64, 256, shmem>>>(G, Atb, rho_p, lam_p, out);
}

// round 3
// speedup vs baseline: 3.1847x; 3.1847x over previous
#include <cuda_runtime.h>
#include <math.h>

#define Mdim 2048
#define Ndim 256
#define Kdim 256
#define ITERS 1000
#define JS 216              // Minv rows resident in SMEM (216 KB)
#define NS_ITERS 12         // Newton-Schulz iterations (converges in ~9)

// Scratch (allocation-free rule: __device__ globals)
__device__ float g_G[Ndim * Ndim];
__device__ float g_Atb[Ndim * Kdim];
__device__ float g_X0[Ndim * Ndim];
__device__ float g_X1[Ndim * Ndim];
__device__ float g_Y[Ndim * Ndim];
__device__ float g_a[1];

// ---------------------------------------------------------------------------
// C = A^T X  (A: [M,N], X: [M,K], C: [N,K]), optionally += rho*I on diagonal
// ---------------------------------------------------------------------------
__global__ void atx_kernel(const float* __restrict__ A, const float* __restrict__ X,
                           float* __restrict__ C, const float* __restrict__ rho_p,
                           int addDiag)
{
    __shared__ float As[32][33];
    __shared__ float Xs[32][33];
    const int tx = threadIdx.x, ty = threadIdx.y;
    const int i0 = blockIdx.x * 32, j0 = blockIdx.y * 32;
    float acc = 0.f;
    for (int mt = 0; mt < Mdim; mt += 32) {
        As[ty][tx] = A[(mt + ty) * Ndim + i0 + tx];
        Xs[ty][tx] = X[(mt + ty) * Kdim + j0 + tx];
        __syncthreads();
#pragma unroll
        for (int mm = 0; mm < 32; mm++)
            acc = fmaf(As[mm][ty], Xs[mm][tx], acc);
        __syncthreads();
    }
    const int i = i0 + ty, j = j0 + tx;
    if (addDiag && i == j) acc += fabsf(rho_p[0]) + 1e-10f;
    C[i * Kdim + j] = acc;
}

// ---------------------------------------------------------------------------
// a = 1/||G||_inf  (G symmetric -> column sums == row sums; read coalesced)
// ---------------------------------------------------------------------------
__global__ void norm_kernel(const float* __restrict__ G, float* __restrict__ a_out)
{
    __shared__ float red[256];
    const int t = threadIdx.x;  // 256 threads, 1 block
    float s = 0.f;
    for (int j = 0; j < Ndim; j++) s += fabsf(G[j * Ndim + t]);
    red[t] = s;
    __syncthreads();
    for (int off = 128; off > 0; off >>= 1) {
        if (t < off) red[t] = fmaxf(red[t], red[t + off]);
        __syncthreads();
    }
    if (t == 0) a_out[0] = 1.0f / red[0];
}

__global__ void init_x_kernel(float* __restrict__ X, const float* __restrict__ a_p)
{
    const int idx = blockIdx.x * blockDim.x + threadIdx.x;  // 64K threads
    const int i = idx >> 8, j = idx & 255;
    X[idx] = (i == j) ? a_p[0] : 0.f;
}

// ---------------------------------------------------------------------------
// 256x256x256 GEMM: mode 0: C = A@B ;  mode 1: C = 2A - A@B  (Newton-Schulz)
// ---------------------------------------------------------------------------
__global__ void gemm256_kernel(const float* __restrict__ A, const float* __restrict__ B,
                               float* __restrict__ C, int ns_mode)
{
    __shared__ float As[32][33];
    __shared__ float Bs[32][33];
    const int tx = threadIdx.x, ty = threadIdx.y;
    const int i = blockIdx.y * 32 + ty, j = blockIdx.x * 32 + tx;
    float acc = 0.f;
    for (int kt = 0; kt < Ndim; kt += 32) {
        As[ty][tx] = A[i * Ndim + kt + tx];
        Bs[ty][tx] = B[(kt + ty) * Ndim + j];
        __syncthreads();
#pragma unroll
        for (int mm = 0; mm < 32; mm++)
            acc = fmaf(As[ty][mm], Bs[mm][tx], acc);
        __syncthreads();
    }
    C[i * Ndim + j] = ns_mode ? fmaf(2.f, A[i * Ndim + j], -acc) : acc;
}

// ---------------------------------------------------------------------------
// Persistent ADMM: 128 blocks x 2 columns, 512 threads.
// Thread = (rowpair rp in [0,128), quarter q in [0,4)); j-range of quarter q
// is the stride-4 comb {q + 4*jj}. jj<54 -> SMEM (rows < 216 exactly);
// jj in [54,64) -> 10 register-resident float2 Minv values (fully unrolled,
// no dynamic indexing -> no local spill).
// Uses Minv symmetry: Tpred[t] = sum_j Minv[j][t] * w[j].
// ---------------------------------------------------------------------------
__global__ void __launch_bounds__(512, 1) admm_kernel(
    const float* __restrict__ Minv, const float* __restrict__ Atb,
    const float* __restrict__ rho_p, const float* __restrict__ lam_p,
    float* __restrict__ out)
{
    extern __shared__ float sm[];
    float*  MinvS = sm;                                   // JS*256 floats
    float2* wbuf  = (float2*)(sm + JS * Ndim);            // [2][256]
    float4* p_s   = (float4*)(sm + JS * Ndim + 2 * 256 * 2); // [3][128]

    const int tid = threadIdx.x;
    const int rp  = tid & 127;
    const int q   = tid >> 7;
    const int r0  = rp * 2;
    const int c0  = blockIdx.x * 2;

    const float rho = fabsf(rho_p[0]) + 1e-10f;
    const float tau = fabsf(lam_p[0]) / rho;

    // Stage Minv rows [0, JS) into SMEM (coalesced float4)
    {
        const float4* src = (const float4*)Minv;
        float4* dst = (float4*)MinvS;
        for (int idx = tid; idx < JS * Ndim / 4; idx += 512) dst[idx] = src[idx];
    }

    // Register tail: j = 216 + q + 4k, k in [0,10)   (covers rows [216,256))
    float2 mt[10];
#pragma unroll
    for (int k = 0; k < 10; k++) {
        const int j = 216 + q + 4 * k;
        mt[k] = make_float2(__ldg(Minv + j * Ndim + r0),
                            __ldg(Minv + j * Ndim + r0 + 1));
    }

    // State owned by q==0 threads: rows r0,r0+1 x cols c0,c0+1
    float2 atb0 = make_float2(0.f, 0.f), atb1 = atb0;
    float2 z0 = atb0, z1 = atb0, u0 = atb0, u1 = atb0;
    float2 tp0 = atb0, tp1 = atb0;
    if (q == 0) {
        atb0 = make_float2(Atb[r0 * Kdim + c0],       Atb[r0 * Kdim + c0 + 1]);
        atb1 = make_float2(Atb[(r0 + 1) * Kdim + c0], Atb[(r0 + 1) * Kdim + c0 + 1]);
        wbuf[r0]     = atb0;   // w = Atb + rho*(0-0)
        wbuf[r0 + 1] = atb1;
    }
    __syncthreads();

    int b = 0;
    for (int it = 0; it < ITERS; ++it) {
        const float2* __restrict__ w = wbuf + b * 256;

        float a00 = 0.f, a01 = 0.f, a10 = 0.f, a11 = 0.f;
#pragma unroll 6
        for (int jj = 0; jj < 54; jj++) {
            const int j = q + 4 * jj;
            const float2 m  = *(const float2*)(MinvS + j * Ndim + r0);
            const float2 wv = w[j];
            a00 = fmaf(m.x, wv.x, a00); a01 = fmaf(m.x, wv.y, a01);
            a10 = fmaf(m.y, wv.x, a10); a11 = fmaf(m.y, wv.y, a11);
        }
#pragma unroll
        for (int k = 0; k < 10; k++) {
            const float2 wv = w[216 + q + 4 * k];
            a00 = fmaf(mt[k].x, wv.x, a00); a01 = fmaf(mt[k].x, wv.y, a01);
            a10 = fmaf(mt[k].y, wv.x, a10); a11 = fmaf(mt[k].y, wv.y, a11);
        }

        if (q) p_s[(q - 1) * 128 + rp] = make_float4(a00, a01, a10, a11);
        __syncthreads();

        if (q == 0) {
#pragma unroll
            for (int s = 0; s < 3; s++) {
                const float4 p = p_s[s * 128 + rp];
                a00 += p.x; a01 += p.y; a10 += p.z; a11 += p.w;
            }
            tp0 = make_float2(a00, a01);
            tp1 = make_float2(a10, a11);

            // soft-threshold + clip + dual update, then next w
            float g, zn;
            g = tp0.x + u0.x; zn = fmaxf(g - tau, 0.f) + fminf(g + tau, 0.f);
            zn = fminf(fmaxf(zn, 0.f), 1.f); u0.x += tp0.x - zn; z0.x = zn;
            g = tp0.y + u0.y; zn = fmaxf(g - tau, 0.f) + fminf(g + tau, 0.f);
            zn = fminf(fmaxf(zn, 0.f), 1.f); u0.y += tp0.y - zn; z0.y = zn;
            g = tp1.x + u1.x; zn = fmaxf(g - tau, 0.f) + fminf(g + tau, 0.f);
            zn = fminf(fmaxf(zn, 0.f), 1.f); u1.x += tp1.x - zn; z1.x = zn;
            g = tp1.y + u1.y; zn = fmaxf(g - tau, 0.f) + fminf(g + tau, 0.f);
            zn = fminf(fmaxf(zn, 0.f), 1.f); u1.y += tp1.y - zn; z1.y = zn;

            float2 wn0, wn1;
            wn0.x = fmaf(rho, z0.x - u0.x, atb0.x);
            wn0.y = fmaf(rho, z0.y - u0.y, atb0.y);
            wn1.x = fmaf(rho, z1.x - u1.x, atb1.x);
            wn1.y = fmaf(rho, z1.y - u1.y, atb1.y);
            wbuf[(b ^ 1) * 256 + r0]     = wn0;
            wbuf[(b ^ 1) * 256 + r0 + 1] = wn1;
        }
        __syncthreads();
        b ^= 1;
    }

    if (q == 0) {
        out[r0 * Kdim + c0]           = tp0.x;
        out[r0 * Kdim + c0 + 1]       = tp0.y;
        out[(r0 + 1) * Kdim + c0]     = tp1.x;
        out[(r0 + 1) * Kdim + c0 + 1] = tp1.y;
    }
}

// ---------------------------------------------------------------------------
extern "C" void kernel_launch(void* const* d_in, const int* in_sizes, int n_in,
                              void* d_out, int out_size)
{
    // metadata order: T, s_A, s_mic_data, rho_param, lam_param
    const float* s_A   = (const float*)d_in[1];
    const float* s_mic = (const float*)d_in[2];
    const float* rho_p = (const float*)d_in[3];
    const float* lam_p = (const float*)d_in[4];
    float* out = (float*)d_out;

    float *G, *Atb, *X0, *X1, *Y, *ap;
    cudaGetSymbolAddress((void**)&G,   g_G);
    cudaGetSymbolAddress((void**)&Atb, g_Atb);
    cudaGetSymbolAddress((void**)&X0,  g_X0);
    cudaGetSymbolAddress((void**)&X1,  g_X1);
    cudaGetSymbolAddress((void**)&Y,   g_Y);
    cudaGetSymbolAddress((void**)&ap,  g_a);

    const size_t shmem = (size_t)(JS * Ndim) * sizeof(float)
                       + 2 * 256 * sizeof(float2) + 3 * 128 * sizeof(float4);
    cudaFuncSetAttribute(admm_kernel, cudaFuncAttributeMaxDynamicSharedMemorySize,
                         (int)shmem);

    dim3 tb(32, 32);
    dim3 gb(8, 8);
    atx_kernel<<<gb, tb>>>(s_A, s_A,   G,   rho_p, 1);
    atx_kernel<<<gb, tb>>>(s_A, s_mic, Atb, rho_p, 0);

    // Newton-Schulz inverse: X0 = I/||G||inf; X <- 2X - X@(G@X), 12 iters
    norm_kernel<<<1, 256>>>(G, ap);
    init_x_kernel<<<256, 256>>>(X0, ap);
    float* Xc = X0; float* Xn = X1;
    for (int i = 0; i < NS_ITERS; i++) {
        gemm256_kernel<<<gb, tb>>>(G,  Xc, Y,  0);  // Y  = G@X
        gemm256_kernel<<<gb, tb>>>(Xc, Y,  Xn, 1);  // Xn = 2X - X@Y
        float* t = Xc; Xc = Xn; Xn = t;
    }
    // NS_ITERS even -> result back in X0 (== Xc)

    admm_kernel<<<128, 512, shmem>>>(Xc, Atb, rho_p, lam_p, out);
}